// round 7
// baseline (speedup 1.0000x reference)
#include <cuda_runtime.h>
#include <math.h>

#define BB 8
#define CC 8
#define HH 256
#define WW 512
#define PLANE (HH*WW)
#define NPIX (BB*PLANE)
#define BANDH 8
#define NROWS (BANDH+2)
#define TX 128                            /* cols per iter CTA */
#define GRID_I (BB*(HH/BANDH)*(WW/TX))    /* 8*32*4 = 1024 */
#define NITER 16
#define FULLMASK 0xffffffffu

// Depth ping-pong scratch (allocation-free).
__device__ float d_bufA[NPIX];            // 4 MB
__device__ float d_bufB[NPIX];            // 4 MB

// ---------------------------------------------------------------------------
// Init: d0 = sparse > 0 ? sparse : blur   (pure elementwise)
// ---------------------------------------------------------------------------
__global__ __launch_bounds__(256) void init_kernel(
    const float* __restrict__ blur,
    const float* __restrict__ sparse)
{
    const int i = blockIdx.x * 256 + threadIdx.x;   // float4 index
    const float4 s = reinterpret_cast<const float4*>(sparse)[i];
    float4 v       = reinterpret_cast<const float4*>(blur)[i];
    v.x = (s.x > 0.f) ? s.x : v.x;
    v.y = (s.y > 0.f) ? s.y : v.y;
    v.z = (s.z > 0.f) ? s.z : v.z;
    v.w = (s.w > 0.f) ? s.w : v.w;
    reinterpret_cast<float4*>(d_bufA)[i] = v;
}

// ---------------------------------------------------------------------------
// One CSPN step:
//   d_new(p) = max_c [ sum_{3x3} g_c(n) d(n) / sum_{3x3} g_c(n) ],  g = |guid|
//   then sparse re-injection.
// 8 warps/CTA = 8 gate channels over an 8x128 tile. Two vec4 loads per row;
// horizontal halos via shfl (edge lanes: predicated scalar loads) to keep the
// L1 wavefront count minimal. Rows are masked via clamped addresses + fp mask
// folded into g (d needs no mask: every u-term carries a g factor).
// ---------------------------------------------------------------------------
__global__ __launch_bounds__(256, 3) void iter_kernel(
    int src_sel,                    // 0: read d_bufA, 1: read d_bufB
    float* __restrict__ dst_ext,    // if non-null, write here (final iter)
    const float* __restrict__ guid,
    const float* __restrict__ sparse)
{
    __shared__ float souts[CC][BANDH][TX]; // per-channel results, 32 KB

    const int tid  = threadIdx.x;
    const int lane = tid & 31;
    const int c    = tid >> 5;             // warp == channel
    const int bid  = blockIdx.x;
    const int xc   = bid & 3;
    const int yb   = (bid >> 2) & 31;
    const int b    = bid >> 7;
    const int x0   = xc * TX;
    const int y0   = yb * BANDH;

    const float* dsrc = src_sel ? d_bufB : d_bufA;
    float*       ddst = dst_ext ? dst_ext : (src_sel ? d_bufA : d_bufB);
    const float* dsb  = dsrc   + (size_t)b * PLANE;
    const float* spb  = sparse + (size_t)b * PLANE;
    float*       ddb  = ddst   + (size_t)b * PLANE;

    // ---- prefetch sparse for the epilogue (independent of everything) ----
    const int ep_row = tid >> 5;           // 0..7
    const int ep_c4  = tid & 31;
    const float4 sp_pre = *reinterpret_cast<const float4*>(
                              spb + (size_t)(y0 + ep_row) * WW + x0 + ep_c4 * 4);

    // ---- this warp's channel: stream 10 rows, rolling vertical sums ----
    const float* gc = guid + ((size_t)(b * CC + c)) * PLANE;
    const int lx = x0 + lane * 4;

    float4 usp = make_float4(0.f,0.f,0.f,0.f), usc = usp;  // u = g*d rowsums
    float4 gsp = make_float4(0.f,0.f,0.f,0.f), gsc = gsp;  // g rowsums

    #pragma unroll
    for (int i = 0; i < NROWS; i++) {
        const int   ry    = y0 - 1 + i;
        const int   ryc   = (ry < 0) ? 0 : ((ry >= HH) ? (HH - 1) : ry);
        const float vmask = (ry >= 0 && ry < HH) ? 1.f : 0.f;
        const size_t ro   = (size_t)ryc * WW;

        // two vec4 loads per row (always in-bounds thanks to clamped row)
        const float4 gr = *reinterpret_cast<const float4*>(gc  + ro + lx);
        const float4 dr = *reinterpret_cast<const float4*>(dsb + ro + lx);

        float4 ga;
        ga.x = fabsf(gr.x) * vmask; ga.y = fabsf(gr.y) * vmask;
        ga.z = fabsf(gr.z) * vmask; ga.w = fabsf(gr.w) * vmask;

        // horizontal halos from neighbor lanes; edge lanes via predicated loads
        float gm1 = __shfl_up_sync  (FULLMASK, ga.w, 1);
        float dm1 = __shfl_up_sync  (FULLMASK, dr.w, 1);
        float gp4 = __shfl_down_sync(FULLMASK, ga.x, 1);
        float dp4 = __shfl_down_sync(FULLMASK, dr.x, 1);
        if (lane == 0) {
            const bool e = (lx > 0);
            gm1 = e ? fabsf(gc[ro + lx - 1]) * vmask : 0.f;
            dm1 = e ?       dsb[ro + lx - 1]         : 0.f;
        }
        if (lane == 31) {
            const bool e = (lx + 4 < WW);
            gp4 = e ? fabsf(gc[ro + lx + 4]) * vmask : 0.f;
            dp4 = e ?       dsb[ro + lx + 4]         : 0.f;
        }

        const float um1 = gm1  * dm1;
        const float u0  = ga.x * dr.x;
        const float u1  = ga.y * dr.y;
        const float u2  = ga.z * dr.z;
        const float u3  = ga.w * dr.w;
        const float up4 = gp4  * dp4;

        float4 usn, gsn;
        {
            const float t01 = u0 + u1, t12 = u1 + u2, t23 = u2 + u3;
            usn.x = um1 + t01; usn.y = t01 + u2;
            usn.z = t12 + u3;  usn.w = t23 + up4;
            const float s01 = ga.x + ga.y, s12 = ga.y + ga.z, s23 = ga.z + ga.w;
            gsn.x = gm1 + s01;  gsn.y = s01 + ga.z;
            gsn.z = s12 + ga.w; gsn.w = s23 + gp4;
        }

        if (i >= 2) {
            float4 o;
            o.x = __fdividef(usp.x + usc.x + usn.x, gsp.x + gsc.x + gsn.x);
            o.y = __fdividef(usp.y + usc.y + usn.y, gsp.y + gsc.y + gsn.y);
            o.z = __fdividef(usp.z + usc.z + usn.z, gsp.z + gsc.z + gsn.z);
            o.w = __fdividef(usp.w + usc.w + usn.w, gsp.w + gsc.w + gsn.w);
            *reinterpret_cast<float4*>(&souts[c][i - 2][lane * 4]) = o;
        }
        usp = usc; usc = usn;
        gsp = gsc; gsc = gsn;
    }
    __syncthreads();

    // ---- 8-way max reduce + sparse re-injection + float4 store ----
    {
        float4 m = *reinterpret_cast<const float4*>(&souts[0][ep_row][ep_c4 * 4]);
        #pragma unroll
        for (int cc = 1; cc < CC; cc++) {
            const float4 v = *reinterpret_cast<const float4*>(&souts[cc][ep_row][ep_c4 * 4]);
            m.x = fmaxf(m.x, v.x); m.y = fmaxf(m.y, v.y);
            m.z = fmaxf(m.z, v.z); m.w = fmaxf(m.w, v.w);
        }
        m.x = (sp_pre.x > 0.f) ? sp_pre.x : m.x;
        m.y = (sp_pre.y > 0.f) ? sp_pre.y : m.y;
        m.z = (sp_pre.z > 0.f) ? sp_pre.z : m.z;
        m.w = (sp_pre.w > 0.f) ? sp_pre.w : m.w;
        *reinterpret_cast<float4*>(ddb + (size_t)(y0 + ep_row) * WW + x0 + ep_c4 * 4) = m;
    }
}

extern "C" void kernel_launch(void* const* d_in, const int* in_sizes, int n_in,
                              void* d_out, int out_size)
{
    const float* guid   = (const float*)d_in[0];
    const float* blur   = (const float*)d_in[1];
    const float* sparse = (const float*)d_in[2];
    float*       out    = (float*)d_out;

    init_kernel<<<NPIX / 4 / 256, 256>>>(blur, sparse);

    // d0 lives in d_bufA. Even i reads A writes B, odd i reads B writes A.
    for (int i = 0; i < NITER; i++) {
        float* dst_ext = (i == NITER - 1) ? out : nullptr;
        iter_kernel<<<GRID_I, 256>>>(i & 1, dst_ext, guid, sparse);
    }
}

// round 8
// speedup vs baseline: 1.5229x; 1.5229x over previous
#include <cuda_runtime.h>
#include <math.h>

#define BB 8
#define CC 8
#define HH 256
#define WW 512
#define PLANE (HH*WW)
#define NPIX (BB*PLANE)
#define BANDH 8
#define NROWS (BANDH+2)
#define TX 128                            /* cols per iter CTA */
#define GRID_I (BB*(HH/BANDH)*(WW/TX))    /* 8*32*4 = 1024 */
#define NITER 16
#define FULLMASK 0xffffffffu

// Depth ping-pong scratch (allocation-free).
__device__ float d_bufA[NPIX];            // 4 MB
__device__ float d_bufB[NPIX];            // 4 MB

// ---------------------------------------------------------------------------
// Init: d0 = sparse > 0 ? sparse : blur   (pure elementwise)
// ---------------------------------------------------------------------------
__global__ __launch_bounds__(256) void init_kernel(
    const float* __restrict__ blur,
    const float* __restrict__ sparse)
{
    const int i = blockIdx.x * 256 + threadIdx.x;   // float4 index
    const float4 s = reinterpret_cast<const float4*>(sparse)[i];
    float4 v       = reinterpret_cast<const float4*>(blur)[i];
    v.x = (s.x > 0.f) ? s.x : v.x;
    v.y = (s.y > 0.f) ? s.y : v.y;
    v.z = (s.z > 0.f) ? s.z : v.z;
    v.w = (s.w > 0.f) ? s.w : v.w;
    reinterpret_cast<float4*>(d_bufA)[i] = v;
}

// ---------------------------------------------------------------------------
// One CSPN step:
//   d_new(p) = max_c [ sum_{3x3} g_c(n) d(n) / sum_{3x3} g_c(n) ],  g = |guid|
//   then sparse re-injection.
// 8 warps/CTA = 8 gate channels over an 8x128 tile. Per row: 2 vec4 LDGs,
// 4 branchless shuffles for interior halos, 4 broadcast (uniform-address,
// 1-wavefront) LDGs for the tile-edge columns, SEL-based edge substitution.
// No divergent branches anywhere in the mainloop.
// ---------------------------------------------------------------------------
__global__ __launch_bounds__(256, 3) void iter_kernel(
    int src_sel,                    // 0: read d_bufA, 1: read d_bufB
    float* __restrict__ dst_ext,    // if non-null, write here (final iter)
    const float* __restrict__ guid,
    const float* __restrict__ sparse)
{
    __shared__ float souts[CC][BANDH][TX]; // per-channel results, 32 KB

    const int tid  = threadIdx.x;
    const int lane = tid & 31;
    const int c    = tid >> 5;             // warp == channel
    const int bid  = blockIdx.x;
    const int xc   = bid & 3;
    const int yb   = (bid >> 2) & 31;
    const int b    = bid >> 7;
    const int x0   = xc * TX;
    const int y0   = yb * BANDH;

    const float* dsrc = src_sel ? d_bufB : d_bufA;
    float*       ddst = dst_ext ? dst_ext : (src_sel ? d_bufA : d_bufB);
    const float* dsb  = dsrc   + (size_t)b * PLANE;
    const float* spb  = sparse + (size_t)b * PLANE;
    float*       ddb  = ddst   + (size_t)b * PLANE;

    // ---- prefetch sparse for the epilogue (independent of everything) ----
    const int ep_row = tid >> 5;           // 0..7
    const int ep_c4  = tid & 31;
    const float4 sp_pre = *reinterpret_cast<const float4*>(
                              spb + (size_t)(y0 + ep_row) * WW + x0 + ep_c4 * 4);

    // ---- this warp's channel: stream 10 rows, rolling vertical sums ----
    const float* gc = guid + ((size_t)(b * CC + c)) * PLANE;
    const int lx = x0 + lane * 4;

    // uniform (per-warp) clamped edge columns + per-lane edge masks (hoisted)
    const int   xm = (x0 > 0)        ? (x0 - 1)  : 0;
    const int   xp = (x0 + TX < WW)  ? (x0 + TX) : (WW - 1);
    const float lm = (lane == 0)  ? ((x0 > 0)       ? 1.f : 0.f) : 1.f;
    const float rm = (lane == 31) ? ((x0 + TX < WW) ? 1.f : 0.f) : 1.f;
    const bool  is_l = (lane == 0);
    const bool  is_r = (lane == 31);

    float4 usp = make_float4(0.f,0.f,0.f,0.f), usc = usp;  // u = g*d rowsums
    float4 gsp = make_float4(0.f,0.f,0.f,0.f), gsc = gsp;  // g rowsums

    #pragma unroll
    for (int i = 0; i < NROWS; i++) {
        const int   ry    = y0 - 1 + i;
        const int   ryc   = (ry < 0) ? 0 : ((ry >= HH) ? (HH - 1) : ry);
        const float vmask = (ry >= 0 && ry < HH) ? 1.f : 0.f;
        const size_t ro   = (size_t)ryc * WW;

        // two vec4 loads + four 1-wavefront broadcast edge loads (all independent)
        const float4 gr  = *reinterpret_cast<const float4*>(gc  + ro + lx);
        const float4 dr  = *reinterpret_cast<const float4*>(dsb + ro + lx);
        const float  geL = gc [ro + xm];
        const float  deL = dsb[ro + xm];
        const float  geR = gc [ro + xp];
        const float  deR = dsb[ro + xp];

        // interior halos via shuffle of RAW values; edge lanes via SEL
        float g_up = __shfl_up_sync  (FULLMASK, gr.w, 1);
        float d_up = __shfl_up_sync  (FULLMASK, dr.w, 1);
        float g_dn = __shfl_down_sync(FULLMASK, gr.x, 1);
        float d_dn = __shfl_down_sync(FULLMASK, dr.x, 1);
        g_up = is_l ? geL : g_up;
        d_up = is_l ? deL : d_up;
        g_dn = is_r ? geR : g_dn;
        d_dn = is_r ? deR : d_dn;

        float4 ga;
        ga.x = fabsf(gr.x) * vmask; ga.y = fabsf(gr.y) * vmask;
        ga.z = fabsf(gr.z) * vmask; ga.w = fabsf(gr.w) * vmask;
        const float gm1 = fabsf(g_up) * (vmask * lm);
        const float gp4 = fabsf(g_dn) * (vmask * rm);

        const float um1 = gm1  * d_up;
        const float u0  = ga.x * dr.x;
        const float u1  = ga.y * dr.y;
        const float u2  = ga.z * dr.z;
        const float u3  = ga.w * dr.w;
        const float up4 = gp4  * d_dn;

        float4 usn, gsn;
        {
            const float t01 = u0 + u1, t12 = u1 + u2, t23 = u2 + u3;
            usn.x = um1 + t01; usn.y = t01 + u2;
            usn.z = t12 + u3;  usn.w = t23 + up4;
            const float s01 = ga.x + ga.y, s12 = ga.y + ga.z, s23 = ga.z + ga.w;
            gsn.x = gm1 + s01;  gsn.y = s01 + ga.z;
            gsn.z = s12 + ga.w; gsn.w = s23 + gp4;
        }

        if (i >= 2) {
            float4 o;
            o.x = __fdividef(usp.x + usc.x + usn.x, gsp.x + gsc.x + gsn.x);
            o.y = __fdividef(usp.y + usc.y + usn.y, gsp.y + gsc.y + gsn.y);
            o.z = __fdividef(usp.z + usc.z + usn.z, gsp.z + gsc.z + gsn.z);
            o.w = __fdividef(usp.w + usc.w + usn.w, gsp.w + gsc.w + gsn.w);
            *reinterpret_cast<float4*>(&souts[c][i - 2][lane * 4]) = o;
        }
        usp = usc; usc = usn;
        gsp = gsc; gsc = gsn;
    }
    __syncthreads();

    // ---- 8-way max reduce + sparse re-injection + float4 store ----
    {
        float4 m = *reinterpret_cast<const float4*>(&souts[0][ep_row][ep_c4 * 4]);
        #pragma unroll
        for (int cc = 1; cc < CC; cc++) {
            const float4 v = *reinterpret_cast<const float4*>(&souts[cc][ep_row][ep_c4 * 4]);
            m.x = fmaxf(m.x, v.x); m.y = fmaxf(m.y, v.y);
            m.z = fmaxf(m.z, v.z); m.w = fmaxf(m.w, v.w);
        }
        m.x = (sp_pre.x > 0.f) ? sp_pre.x : m.x;
        m.y = (sp_pre.y > 0.f) ? sp_pre.y : m.y;
        m.z = (sp_pre.z > 0.f) ? sp_pre.z : m.z;
        m.w = (sp_pre.w > 0.f) ? sp_pre.w : m.w;
        *reinterpret_cast<float4*>(ddb + (size_t)(y0 + ep_row) * WW + x0 + ep_c4 * 4) = m;
    }
}

extern "C" void kernel_launch(void* const* d_in, const int* in_sizes, int n_in,
                              void* d_out, int out_size)
{
    const float* guid   = (const float*)d_in[0];
    const float* blur   = (const float*)d_in[1];
    const float* sparse = (const float*)d_in[2];
    float*       out    = (float*)d_out;

    init_kernel<<<NPIX / 4 / 256, 256>>>(blur, sparse);

    // d0 lives in d_bufA. Even i reads A writes B, odd i reads B writes A.
    for (int i = 0; i < NITER; i++) {
        float* dst_ext = (i == NITER - 1) ? out : nullptr;
        iter_kernel<<<GRID_I, 256>>>(i & 1, dst_ext, guid, sparse);
    }
}

// round 9
// speedup vs baseline: 1.5746x; 1.0339x over previous
#include <cuda_runtime.h>
#include <math.h>

#define BB 8
#define CC 8
#define HH 256
#define WW 512
#define PLANE (HH*WW)
#define NPIX (BB*PLANE)
#define BANDH 8
#define NROWS (BANDH+2)
#define TX 128                            /* cols per iter CTA */
#define GRID_I (BB*(HH/BANDH)*(WW/TX))    /* 8*32*4 = 1024 */
#define NITER 16
#define FULLMASK 0xffffffffu

// Depth ping-pong scratch (allocation-free).
__device__ float d_bufA[NPIX];            // 4 MB
__device__ float d_bufB[NPIX];            // 4 MB

// ---------------------------------------------------------------------------
// Init: d0 = sparse > 0 ? sparse : blur   (pure elementwise)
// ---------------------------------------------------------------------------
__global__ __launch_bounds__(256) void init_kernel(
    const float* __restrict__ blur,
    const float* __restrict__ sparse)
{
    const int i = blockIdx.x * 256 + threadIdx.x;   // float4 index
    const float4 s = reinterpret_cast<const float4*>(sparse)[i];
    float4 v       = reinterpret_cast<const float4*>(blur)[i];
    v.x = (s.x > 0.f) ? s.x : v.x;
    v.y = (s.y > 0.f) ? s.y : v.y;
    v.z = (s.z > 0.f) ? s.z : v.z;
    v.w = (s.w > 0.f) ? s.w : v.w;
    reinterpret_cast<float4*>(d_bufA)[i] = v;
}

// ---------------------------------------------------------------------------
// One CSPN step:
//   d_new(p) = max_c [ sum_{3x3} g_c(n) d(n) / sum_{3x3} g_c(n) ],  g = |guid|
//   then sparse re-injection.
// 8 warps/CTA = 8 gate channels over an 8x128 tile. Tile-edge halo columns
// are preloaded cooperatively into smem (one-time), so the mainloop is just
// 2 vec4 LDGs + 4 shuffles + 4 broadcast LDS per row — minimal registers,
// no divergent branches, 4 CTAs/SM.
// ---------------------------------------------------------------------------
__global__ __launch_bounds__(256, 4) void iter_kernel(
    int src_sel,                    // 0: read d_bufA, 1: read d_bufB
    float* __restrict__ dst_ext,    // if non-null, write here (final iter)
    const float* __restrict__ guid,
    const float* __restrict__ sparse)
{
    __shared__ float souts[CC][BANDH][TX]; // per-channel results, 32 KB
    __shared__ float sEg[CC][NROWS][2];    // g edge halos (raw values)
    __shared__ float sEd[NROWS][2];        // d edge halos

    const int tid  = threadIdx.x;
    const int lane = tid & 31;
    const int c    = tid >> 5;             // warp == channel
    const int bid  = blockIdx.x;
    const int xc   = bid & 3;
    const int yb   = (bid >> 2) & 31;
    const int b    = bid >> 7;
    const int x0   = xc * TX;
    const int y0   = yb * BANDH;

    const float* dsrc = src_sel ? d_bufB : d_bufA;
    float*       ddst = dst_ext ? dst_ext : (src_sel ? d_bufA : d_bufB);
    const float* dsb  = dsrc   + (size_t)b * PLANE;
    const float* spb  = sparse + (size_t)b * PLANE;
    float*       ddb  = ddst   + (size_t)b * PLANE;

    // uniform clamped edge columns for this CTA
    const int xm = (x0 > 0)       ? (x0 - 1)  : 0;
    const int xp = (x0 + TX < WW) ? (x0 + TX) : (WW - 1);

    // ---- one-time cooperative preload of edge halo columns ----
    if (tid < CC * NROWS * 2 + NROWS * 2) {            // 180 threads
        if (tid < CC * NROWS * 2) {
            const int ec = tid / (NROWS * 2);
            const int er = (tid >> 1) % NROWS;
            const int es = tid & 1;
            const int ry = y0 - 1 + er;
            const int ryc = (ry < 0) ? 0 : ((ry >= HH) ? (HH - 1) : ry);
            sEg[ec][er][es] = guid[((size_t)(b * CC + ec)) * PLANE
                                   + (size_t)ryc * WW + (es ? xp : xm)];
        } else {
            const int t  = tid - CC * NROWS * 2;
            const int er = t >> 1;
            const int es = t & 1;
            const int ry = y0 - 1 + er;
            const int ryc = (ry < 0) ? 0 : ((ry >= HH) ? (HH - 1) : ry);
            sEd[er][es] = dsb[(size_t)ryc * WW + (es ? xp : xm)];
        }
    }

    // ---- prefetch sparse for the epilogue (independent of everything) ----
    const int ep_row = tid >> 5;           // 0..7
    const int ep_c4  = tid & 31;
    const float4 sp_pre = *reinterpret_cast<const float4*>(
                              spb + (size_t)(y0 + ep_row) * WW + x0 + ep_c4 * 4);

    __syncthreads();

    // ---- this warp's channel: stream 10 rows, rolling vertical sums ----
    const float* gc = guid + ((size_t)(b * CC + c)) * PLANE;
    const int lx = x0 + lane * 4;

    // per-lane edge masks (hoisted)
    const float lm = (lane == 0)  ? ((x0 > 0)       ? 1.f : 0.f) : 1.f;
    const float rm = (lane == 31) ? ((x0 + TX < WW) ? 1.f : 0.f) : 1.f;
    const bool  is_l = (lane == 0);
    const bool  is_r = (lane == 31);

    float4 usp = make_float4(0.f,0.f,0.f,0.f), usc = usp;  // u = g*d rowsums
    float4 gsp = make_float4(0.f,0.f,0.f,0.f), gsc = gsp;  // g rowsums

    #pragma unroll
    for (int i = 0; i < NROWS; i++) {
        const int   ry    = y0 - 1 + i;
        const int   ryc   = (ry < 0) ? 0 : ((ry >= HH) ? (HH - 1) : ry);
        const float vmask = (ry >= 0 && ry < HH) ? 1.f : 0.f;
        const size_t ro   = (size_t)ryc * WW;

        // two vec4 loads (always in-bounds thanks to clamped row)
        const float4 gr = *reinterpret_cast<const float4*>(gc  + ro + lx);
        const float4 dr = *reinterpret_cast<const float4*>(dsb + ro + lx);

        // interior halos via shuffle of RAW values; edge lanes via smem + SEL
        float g_up = __shfl_up_sync  (FULLMASK, gr.w, 1);
        float d_up = __shfl_up_sync  (FULLMASK, dr.w, 1);
        float g_dn = __shfl_down_sync(FULLMASK, gr.x, 1);
        float d_dn = __shfl_down_sync(FULLMASK, dr.x, 1);
        g_up = is_l ? sEg[c][i][0] : g_up;
        d_up = is_l ? sEd[i][0]    : d_up;
        g_dn = is_r ? sEg[c][i][1] : g_dn;
        d_dn = is_r ? sEd[i][1]    : d_dn;

        float4 ga;
        ga.x = fabsf(gr.x) * vmask; ga.y = fabsf(gr.y) * vmask;
        ga.z = fabsf(gr.z) * vmask; ga.w = fabsf(gr.w) * vmask;
        const float gm1 = fabsf(g_up) * (vmask * lm);
        const float gp4 = fabsf(g_dn) * (vmask * rm);

        const float um1 = gm1  * d_up;
        const float u0  = ga.x * dr.x;
        const float u1  = ga.y * dr.y;
        const float u2  = ga.z * dr.z;
        const float u3  = ga.w * dr.w;
        const float up4 = gp4  * d_dn;

        float4 usn, gsn;
        {
            const float t01 = u0 + u1, t12 = u1 + u2, t23 = u2 + u3;
            usn.x = um1 + t01; usn.y = t01 + u2;
            usn.z = t12 + u3;  usn.w = t23 + up4;
            const float s01 = ga.x + ga.y, s12 = ga.y + ga.z, s23 = ga.z + ga.w;
            gsn.x = gm1 + s01;  gsn.y = s01 + ga.z;
            gsn.z = s12 + ga.w; gsn.w = s23 + gp4;
        }

        if (i >= 2) {
            float4 o;
            o.x = __fdividef(usp.x + usc.x + usn.x, gsp.x + gsc.x + gsn.x);
            o.y = __fdividef(usp.y + usc.y + usn.y, gsp.y + gsc.y + gsn.y);
            o.z = __fdividef(usp.z + usc.z + usn.z, gsp.z + gsc.z + gsn.z);
            o.w = __fdividef(usp.w + usc.w + usn.w, gsp.w + gsc.w + gsn.w);
            *reinterpret_cast<float4*>(&souts[c][i - 2][lane * 4]) = o;
        }
        usp = usc; usc = usn;
        gsp = gsc; gsc = gsn;
    }
    __syncthreads();

    // ---- 8-way max reduce + sparse re-injection + float4 store ----
    {
        float4 m = *reinterpret_cast<const float4*>(&souts[0][ep_row][ep_c4 * 4]);
        #pragma unroll
        for (int cc = 1; cc < CC; cc++) {
            const float4 v = *reinterpret_cast<const float4*>(&souts[cc][ep_row][ep_c4 * 4]);
            m.x = fmaxf(m.x, v.x); m.y = fmaxf(m.y, v.y);
            m.z = fmaxf(m.z, v.z); m.w = fmaxf(m.w, v.w);
        }
        m.x = (sp_pre.x > 0.f) ? sp_pre.x : m.x;
        m.y = (sp_pre.y > 0.f) ? sp_pre.y : m.y;
        m.z = (sp_pre.z > 0.f) ? sp_pre.z : m.z;
        m.w = (sp_pre.w > 0.f) ? sp_pre.w : m.w;
        *reinterpret_cast<float4*>(ddb + (size_t)(y0 + ep_row) * WW + x0 + ep_c4 * 4) = m;
    }
}

extern "C" void kernel_launch(void* const* d_in, const int* in_sizes, int n_in,
                              void* d_out, int out_size)
{
    const float* guid   = (const float*)d_in[0];
    const float* blur   = (const float*)d_in[1];
    const float* sparse = (const float*)d_in[2];
    float*       out    = (float*)d_out;

    init_kernel<<<NPIX / 4 / 256, 256>>>(blur, sparse);

    // d0 lives in d_bufA. Even i reads A writes B, odd i reads B writes A.
    for (int i = 0; i < NITER; i++) {
        float* dst_ext = (i == NITER - 1) ? out : nullptr;
        iter_kernel<<<GRID_I, 256>>>(i & 1, dst_ext, guid, sparse);
    }
}